// round 7
// baseline (speedup 1.0000x reference)
#include <cuda_runtime.h>
#include <cuda_bf16.h>

#define NN 50000
#define NE 600000
#define CC 128
#define NG 64
#define EPSV 1e-5f
#define NB 196      // ceil(NN/256)
#define AGB 6250    // NN/8 aggregate blocks

// ---------------- scratch (device globals; no allocs allowed) ----------------
__device__ unsigned int g_hb[NN * 64];   // GEMM output, bf16x2 packed (2 ch/uint)
__device__ float g_agg[NN * CC];         // aggregated messages (pre-BN), fp32
__device__ int   g_degi[NN];
__device__ float g_dinv[NN];
__device__ int   g_off[NN + 1];
__device__ int   g_cursor[NN];
__device__ int   g_bsum[256];
__device__ int2  g_edge[NE];             // CSR payload: {src, f32bits(weight)}
__device__ float g_sum[CC];              // BN accumulators (reset by finalize)
__device__ float g_sumsq[CC];
__device__ float g_scale[CC];
__device__ float g_shift[CC];
__device__ int   g_is64;                 // edge_index dtype flag
__device__ int   g_bis64;                // batch dtype flag
__device__ int   g_cnt = 0;              // aggregate last-block counter

// ---------------- packed f32x2 helpers (sm_103a) ----------------
__device__ __forceinline__ unsigned long long bcast2(float x) {
    unsigned long long r;
    asm("mov.b64 %0, {%1, %1};" : "=l"(r) : "f"(x));
    return r;
}
__device__ __forceinline__ void fma2(unsigned long long& d,
                                     unsigned long long a,
                                     unsigned long long b) {
    asm("fma.rn.f32x2 %0, %1, %2, %0;" : "+l"(d) : "l"(a), "l"(b));
}
union U64F2 { unsigned long long u; float2 f; };

// ---------------- zero + dtype detection ----------------
// edge_index: random values in [0,NN) -> int64 iff all 16 sampled interleaved
// high words are zero. batch: sorted (head all zeros; use the tail): word
// [NN-1] readable under either width; int64 -> high word of elem 24999 (0)
// while word [NN-2] (its low word, mid graph id) is nonzero w.h.p.; int32 ->
// batch[NN-1] ~ 63 (nonzero w.h.p.).
__global__ void zero_prep_kernel(const int* ei32, const int* b32) {
    int i = blockIdx.x * blockDim.x + threadIdx.x;
    if (i < NN) { g_degi[i] = 0; g_cursor[i] = 0; }
    if (blockIdx.x == 0 && threadIdx.x == 0) {
        int z = 1;
        #pragma unroll
        for (int k = 0; k < 16; k++)
            if (ei32[2 * k + 1] != 0) z = 0;
        g_is64 = z;
        g_bis64 = (b32[NN - 1] == 0 && b32[NN - 2] != 0) ? 1 : 0;
    }
}

// degree count only (src not needed until fill, which re-decodes)
__global__ void prep_kernel(const void* ei_raw) {
    int e = blockIdx.x * blockDim.x + threadIdx.x;
    if (e >= NE) return;
    int d;
    if (g_is64) d = (int)((const long long*)ei_raw)[NE + e];
    else        d = ((const int*)ei_raw)[NE + e];
    atomicAdd(&g_degi[d], 1);
}

// ---------------- CSR build: scan (dinv fused), then fused scan2+3 ----------
__global__ void scan1_kernel() {
    __shared__ int sh[256];
    int t = threadIdx.x;
    int i = blockIdx.x * 256 + t;
    int v = (i < NN) ? g_degi[i] : 0;
    if (i < NN) g_dinv[i] = (v > 0) ? rsqrtf((float)v) : 0.0f;
    sh[t] = v;
    __syncthreads();
    #pragma unroll
    for (int off = 1; off < 256; off <<= 1) {
        int tmp = (t >= off) ? sh[t - off] : 0;
        __syncthreads();
        sh[t] += tmp;
        __syncthreads();
    }
    if (i < NN) g_off[i] = sh[t] - v;      // exclusive within block
    if (t == 255) g_bsum[blockIdx.x] = sh[255];
}

// every block redundantly scans the 196 block sums (cheap), adds its base
__global__ void scan23_kernel() {
    __shared__ int sh[256];
    int t = threadIdx.x;
    int v = (t < NB) ? g_bsum[t] : 0;
    sh[t] = v;
    __syncthreads();
    #pragma unroll
    for (int off = 1; off < 256; off <<= 1) {
        int tmp = (t >= off) ? sh[t - off] : 0;
        __syncthreads();
        sh[t] += tmp;
        __syncthreads();
    }
    int base = (blockIdx.x == 0) ? 0 : sh[blockIdx.x - 1];  // exclusive prefix
    int i = blockIdx.x * 256 + t;
    if (i < NN) g_off[i] += base;
    if (i == 0) g_off[NN] = NE;
}

// fill CSR slots; decodes edge_index directly; weight dinv[s]*dinv[d] inline
__global__ void fill_kernel(const void* ei_raw) {
    int e = blockIdx.x * blockDim.x + threadIdx.x;
    if (e >= NE) return;
    int s, d;
    if (g_is64) {
        const long long* p = (const long long*)ei_raw;
        s = (int)p[e]; d = (int)p[NE + e];
    } else {
        const int* p = (const int*)ei_raw;
        s = p[e]; d = p[NE + e];
    }
    float w = g_dinv[s] * g_dinv[d];
    int p2 = atomicAdd(&g_cursor[d], 1);
    g_edge[g_off[d] + p2] = make_int2(s, __float_as_int(w));
}

// ---------------- GEMM: [NN,128] @ [128,128] -> g_hb (bf16x2) ---------------
// fuse==1: A = relu(g_agg * g_scale + g_shift) applied inline on load (BN of
// the previous layer). fuse==0: A = Xext (raw input features).
__global__ void __launch_bounds__(256) gemm_kernel(const float* __restrict__ Xext,
                                                   const float* __restrict__ W,
                                                   int fuse) {
    const float* A = fuse ? (const float*)g_agg : Xext;
    __shared__ __align__(16) float Ws[16][128];
    __shared__ __align__(16) float As[16][132];  // 528B row stride (16B mult)
    int tid = threadIdx.x;
    int m0 = blockIdx.x * 128;
    int tx = tid & 15, ty = tid >> 4;

    unsigned long long acc2[8][4];
    #pragma unroll
    for (int i = 0; i < 8; i++)
        #pragma unroll
        for (int j = 0; j < 4; j++) acc2[i][j] = 0ULL;  // {+0.f, +0.f}

    for (int kk = 0; kk < 128; kk += 16) {
        #pragma unroll
        for (int p = 0; p < 2; p++) {
            int f = tid * 2 + p;
            int k = f >> 5, n4 = f & 31;
            ((float4*)Ws[k])[n4] = ((const float4*)W)[(kk + k) * 32 + n4];
        }
        #pragma unroll
        for (int p = 0; p < 2; p++) {
            int f = tid * 2 + p;
            int r = f >> 2, c4 = f & 3;
            int row = m0 + r;
            int col = kk + c4 * 4;
            float4 v = make_float4(0.f, 0.f, 0.f, 0.f);
            if (row < NN) v = *(const float4*)(A + row * CC + col);
            if (fuse) {
                float4 sc = *(const float4*)(g_scale + col);
                float4 sh = *(const float4*)(g_shift + col);
                v.x = fmaxf(fmaf(v.x, sc.x, sh.x), 0.f);
                v.y = fmaxf(fmaf(v.y, sc.y, sh.y), 0.f);
                v.z = fmaxf(fmaf(v.z, sc.z, sh.z), 0.f);
                v.w = fmaxf(fmaf(v.w, sc.w, sh.w), 0.f);
            }
            As[c4 * 4 + 0][r] = v.x;
            As[c4 * 4 + 1][r] = v.y;
            As[c4 * 4 + 2][r] = v.z;
            As[c4 * 4 + 3][r] = v.w;
        }
        __syncthreads();
        #pragma unroll
        for (int k = 0; k < 16; k++) {
            float a[8];
            unsigned long long bb[4];
            *(float4*)(a)     = *(float4*)&As[k][ty * 4];
            *(float4*)(a + 4) = *(float4*)&As[k][64 + ty * 4];
            {
                ulonglong2 t0 = *(ulonglong2*)&Ws[k][tx * 4];
                ulonglong2 t1 = *(ulonglong2*)&Ws[k][64 + tx * 4];
                bb[0] = t0.x; bb[1] = t0.y; bb[2] = t1.x; bb[3] = t1.y;
            }
            #pragma unroll
            for (int i = 0; i < 8; i++) {
                unsigned long long ai = bcast2(a[i]);
                fma2(acc2[i][0], ai, bb[0]);
                fma2(acc2[i][1], ai, bb[1]);
                fma2(acc2[i][2], ai, bb[2]);
                fma2(acc2[i][3], ai, bb[3]);
            }
        }
        __syncthreads();
    }
    #pragma unroll
    for (int i = 0; i < 8; i++) {
        int row = m0 + ((i < 4) ? (ty * 4 + i) : (64 + ty * 4 + (i - 4)));
        if (row < NN) {
            U64F2 p0, p1, p2, p3;
            p0.u = acc2[i][0]; p1.u = acc2[i][1];
            p2.u = acc2[i][2]; p3.u = acc2[i][3];
            __nv_bfloat162 b0 = __floats2bfloat162_rn(p0.f.x, p0.f.y);
            __nv_bfloat162 b1 = __floats2bfloat162_rn(p1.f.x, p1.f.y);
            __nv_bfloat162 b2 = __floats2bfloat162_rn(p2.f.x, p2.f.y);
            __nv_bfloat162 b3 = __floats2bfloat162_rn(p3.f.x, p3.f.y);
            unsigned int u0 = *(unsigned int*)&b0;
            unsigned int u1 = *(unsigned int*)&b1;
            unsigned int u2 = *(unsigned int*)&b2;
            unsigned int u3 = *(unsigned int*)&b3;
            *(uint2*)(g_hb + row * 64 + tx * 2)      = make_uint2(u0, u1);
            *(uint2*)(g_hb + row * 64 + 32 + tx * 2) = make_uint2(u2, u3);
        }
    }
}

// ---------------- aggregation + fused BN stats + last-block finalize --------
// 64 threads/node, 2 channels each; 8 nodes per 512-thr block; grid = AGB.
// Protocol: each block issues its 128 partial atomics, threadfences, then
// thread 0 bumps g_cnt. The block observing g_cnt==AGB-1 is last; all prior
// blocks' L2 atomics are visible to it. It reads totals via atomicAdd(+0.0)
// (L2-coherent read), writes scale/shift, and resets accumulators + counter
// so the kernel is replay-deterministic under CUDA graph capture.
__global__ void __launch_bounds__(512) aggregate_kernel(const float* __restrict__ gam,
                                                        const float* __restrict__ bet) {
    __shared__ float2 sv[512];
    __shared__ int slast;
    int t = threadIdx.x;
    int node = blockIdx.x * 8 + (t >> 6);   // grid exact: AGB*8 == NN
    int c = t & 63;
    int s = g_off[node], e = g_off[node + 1];
    float ax0 = 0.f, ay0 = 0.f, ax1 = 0.f, ay1 = 0.f;
    int j = s;
    for (; j + 1 < e; j += 2) {
        int2 e0 = g_edge[j];
        int2 e1 = g_edge[j + 1];
        unsigned int u0 = g_hb[e0.x * 64 + c];
        unsigned int u1 = g_hb[e1.x * 64 + c];
        float2 f0 = __bfloat1622float2(*(__nv_bfloat162*)&u0);
        float2 f1 = __bfloat1622float2(*(__nv_bfloat162*)&u1);
        float w0 = __int_as_float(e0.y);
        float w1 = __int_as_float(e1.y);
        ax0 += w0 * f0.x; ay0 += w0 * f0.y;
        ax1 += w1 * f1.x; ay1 += w1 * f1.y;
    }
    if (j < e) {
        int2 e0 = g_edge[j];
        unsigned int u0 = g_hb[e0.x * 64 + c];
        float2 f0 = __bfloat1622float2(*(__nv_bfloat162*)&u0);
        float w0 = __int_as_float(e0.y);
        ax0 += w0 * f0.x; ay0 += w0 * f0.y;
    }
    float r0 = ax0 + ax1, r1 = ay0 + ay1;
    *(float2*)(g_agg + node * CC + 2 * c) = make_float2(r0, r1);

    // block-level BN partials: channel t <- sum over the 8 node-groups
    sv[t] = make_float2(r0, r1);
    __syncthreads();
    if (t < 128) {
        float s1 = 0.f, s2 = 0.f;
        #pragma unroll
        for (int gsl = 0; gsl < 8; gsl++) {
            float2 v2 = sv[gsl * 64 + (t >> 1)];
            float v = (t & 1) ? v2.y : v2.x;
            s1 += v; s2 += v * v;
        }
        atomicAdd(&g_sum[t], s1);
        atomicAdd(&g_sumsq[t], s2);
    }
    __threadfence();
    __syncthreads();
    if (t == 0) slast = (atomicAdd(&g_cnt, 1) == AGB - 1) ? 1 : 0;
    __syncthreads();
    if (slast) {
        if (t == 0) g_cnt = 0;                        // reset for replay
        if (t < 128) {
            float ts  = atomicAdd(&g_sum[t], 0.0f);   // coherent L2 read
            float ts2 = atomicAdd(&g_sumsq[t], 0.0f);
            float mu = ts * (1.0f / NN);
            float var = fmaxf(ts2 * (1.0f / NN) - mu * mu, 0.f);
            float sc = gam[t] * rsqrtf(var + EPSV);
            g_scale[t] = sc;
            g_shift[t] = bet[t] - mu * sc;
            g_sum[t] = 0.f;                           // reset for next layer
            g_sumsq[t] = 0.f;
        }
    }
}

// ---------------- pool + head (512 thr; bounds inlined; layer-3 BN fused) ---
__global__ void __launch_bounds__(512) pool_head_kernel(const void* batch_raw,
                                                        const float* __restrict__ Wh,
                                                        const float* __restrict__ bh,
                                                        float* __restrict__ out) {
    __shared__ float part[512];
    __shared__ float pooled[CC];
    __shared__ int sb[2];
    int g = blockIdx.x;
    int t = threadIdx.x;
    int c = t & 127;
    int sub = t >> 7;  // 0..3
    if (t < 2) {
        int target = g + t;
        int lo = 0, hi = NN;
        if (g_bis64) {
            const long long* b = (const long long*)batch_raw;
            while (lo < hi) { int mid = (lo + hi) >> 1; if (b[mid] < (long long)target) lo = mid + 1; else hi = mid; }
        } else {
            const int* b = (const int*)batch_raw;
            while (lo < hi) { int mid = (lo + hi) >> 1; if (b[mid] < target) lo = mid + 1; else hi = mid; }
        }
        sb[t] = lo;
    }
    __syncthreads();
    int s = sb[0], e = sb[1];
    float sc = g_scale[c], sh = g_shift[c];
    float a = 0.f;
    for (int r = s + sub; r < e; r += 4)
        a += fmaxf(fmaf(g_agg[r * CC + c], sc, sh), 0.f);
    part[t] = a;
    __syncthreads();
    if (t < 128) {
        float cnt = (float)(e - s);
        pooled[t] = (part[t] + part[t + 128] + part[t + 256] + part[t + 384])
                    / fmaxf(cnt, 1.0f);
    }
    __syncthreads();
    if (t < 8) {
        float o = bh[t];
        #pragma unroll 8
        for (int k = 0; k < CC; k++) o += pooled[k] * Wh[k * 8 + t];
        out[g * 8 + t] = o;
    }
}

// ---------------- launch ----------------
extern "C" void kernel_launch(void* const* d_in, const int* in_sizes, int n_in,
                              void* d_out, int out_size) {
    const float* x  = (const float*)d_in[0];
    const void*  ei = d_in[1];
    const void*  batch = d_in[2];
    const float* W[3]  = { (const float*)d_in[3],  (const float*)d_in[7],  (const float*)d_in[11] };
    const float* gg[3] = { (const float*)d_in[5],  (const float*)d_in[9],  (const float*)d_in[13] };
    const float* be[3] = { (const float*)d_in[6],  (const float*)d_in[10], (const float*)d_in[14] };
    const float* Wh = (const float*)d_in[15];
    const float* bh = (const float*)d_in[16];
    float* out = (float*)d_out;

    const int EB = (NE + 255) / 256;   // 2344

    zero_prep_kernel<<<NB, 256>>>((const int*)ei, (const int*)batch);
    prep_kernel<<<EB, 256>>>(ei);
    scan1_kernel<<<NB, 256>>>();
    scan23_kernel<<<NB, 256>>>();
    fill_kernel<<<EB, 256>>>(ei);

    for (int l = 0; l < 3; l++) {
        gemm_kernel<<<(NN + 127) / 128, 256>>>(x, W[l], l == 0 ? 0 : 1);
        aggregate_kernel<<<AGB, 512>>>(gg[l], be[l]);
    }

    pool_head_kernel<<<NG, 512>>>(batch, Wh, bh, out);
}

// round 8
// speedup vs baseline: 1.2060x; 1.2060x over previous
#include <cuda_runtime.h>
#include <cuda_bf16.h>

#define NN 50000
#define NE 600000
#define CC 128
#define NG 64
#define EPSV 1e-5f
#define NB 196      // ceil(NN/256)
#define AGB 6250    // NN/8 aggregate blocks
#define SBLK 200    // stats grid

// ---------------- scratch (device globals; no allocs allowed) ----------------
__device__ unsigned int g_hb[NN * 64];   // GEMM output, bf16x2 packed (2 ch/uint)
__device__ float g_agg[NN * CC];         // aggregated messages (pre-BN), fp32
__device__ int   g_degi[NN];
__device__ float g_dinv[NN];
__device__ int   g_off[NN + 1];
__device__ int   g_cursor[NN];
__device__ int   g_bsum[256];
__device__ int2  g_edge[NE];             // CSR payload: {src, f32bits(weight)}
__device__ float g_psum[SBLK * CC];
__device__ float g_psq[SBLK * CC];
__device__ float g_scale[CC];
__device__ float g_shift[CC];
__device__ int   g_is64;                 // edge_index dtype flag
__device__ int   g_bis64;                // batch dtype flag
__device__ int   g_cnt = 0;              // stats last-block counter

// ---------------- packed f32x2 helpers (sm_103a) ----------------
__device__ __forceinline__ unsigned long long bcast2(float x) {
    unsigned long long r;
    asm("mov.b64 %0, {%1, %1};" : "=l"(r) : "f"(x));
    return r;
}
__device__ __forceinline__ void fma2(unsigned long long& d,
                                     unsigned long long a,
                                     unsigned long long b) {
    asm("fma.rn.f32x2 %0, %1, %2, %0;" : "+l"(d) : "l"(a), "l"(b));
}
union U64F2 { unsigned long long u; float2 f; };

// ---------------- zero + dtype detection ----------------
// edge_index: random values in [0,NN) -> int64 iff all 16 sampled interleaved
// high words are zero. batch: sorted (head all zeros; use the tail): word
// [NN-1] readable under either width; int64 -> high word of elem 24999 (0)
// while word [NN-2] (its low word, mid graph id) is nonzero w.h.p.; int32 ->
// batch[NN-1] ~ 63 (nonzero w.h.p.).
__global__ void zero_prep_kernel(const int* ei32, const int* b32) {
    int i = blockIdx.x * blockDim.x + threadIdx.x;
    if (i < NN) { g_degi[i] = 0; g_cursor[i] = 0; }
    if (blockIdx.x == 0 && threadIdx.x == 0) {
        int z = 1;
        #pragma unroll
        for (int k = 0; k < 16; k++)
            if (ei32[2 * k + 1] != 0) z = 0;
        g_is64 = z;
        g_bis64 = (b32[NN - 1] == 0 && b32[NN - 2] != 0) ? 1 : 0;
    }
}

// degree count only (src not needed until fill, which re-decodes)
__global__ void prep_kernel(const void* ei_raw) {
    int e = blockIdx.x * blockDim.x + threadIdx.x;
    if (e >= NE) return;
    int d;
    if (g_is64) d = (int)((const long long*)ei_raw)[NE + e];
    else        d = ((const int*)ei_raw)[NE + e];
    atomicAdd(&g_degi[d], 1);
}

// ---------------- CSR build: scan (dinv fused), then fused scan2+3 ----------
__global__ void scan1_kernel() {
    __shared__ int sh[256];
    int t = threadIdx.x;
    int i = blockIdx.x * 256 + t;
    int v = (i < NN) ? g_degi[i] : 0;
    if (i < NN) g_dinv[i] = (v > 0) ? rsqrtf((float)v) : 0.0f;
    sh[t] = v;
    __syncthreads();
    #pragma unroll
    for (int off = 1; off < 256; off <<= 1) {
        int tmp = (t >= off) ? sh[t - off] : 0;
        __syncthreads();
        sh[t] += tmp;
        __syncthreads();
    }
    if (i < NN) g_off[i] = sh[t] - v;      // exclusive within block
    if (t == 255) g_bsum[blockIdx.x] = sh[255];
}

// every block redundantly scans the 196 block sums (cheap), adds its base
__global__ void scan23_kernel() {
    __shared__ int sh[256];
    int t = threadIdx.x;
    int v = (t < NB) ? g_bsum[t] : 0;
    sh[t] = v;
    __syncthreads();
    #pragma unroll
    for (int off = 1; off < 256; off <<= 1) {
        int tmp = (t >= off) ? sh[t - off] : 0;
        __syncthreads();
        sh[t] += tmp;
        __syncthreads();
    }
    int base = (blockIdx.x == 0) ? 0 : sh[blockIdx.x - 1];  // exclusive prefix
    int i = blockIdx.x * 256 + t;
    if (i < NN) g_off[i] += base;
    if (i == 0) g_off[NN] = NE;
}

// fill CSR slots; decodes edge_index directly; weight dinv[s]*dinv[d] inline
__global__ void fill_kernel(const void* ei_raw) {
    int e = blockIdx.x * blockDim.x + threadIdx.x;
    if (e >= NE) return;
    int s, d;
    if (g_is64) {
        const long long* p = (const long long*)ei_raw;
        s = (int)p[e]; d = (int)p[NE + e];
    } else {
        const int* p = (const int*)ei_raw;
        s = p[e]; d = p[NE + e];
    }
    float w = g_dinv[s] * g_dinv[d];
    int p2 = atomicAdd(&g_cursor[d], 1);
    g_edge[g_off[d] + p2] = make_int2(s, __float_as_int(w));
}

// ---------------- GEMM: [NN,128] @ [128,128] -> g_hb (bf16x2) ---------------
// fuse==1: A = relu(g_agg * g_scale + g_shift) applied inline on load (BN of
// the previous layer). fuse==0: A = Xext (raw input features).
__global__ void __launch_bounds__(256) gemm_kernel(const float* __restrict__ Xext,
                                                   const float* __restrict__ W,
                                                   int fuse) {
    const float* A = fuse ? (const float*)g_agg : Xext;
    __shared__ __align__(16) float Ws[16][128];
    __shared__ __align__(16) float As[16][132];  // 528B row stride (16B mult)
    int tid = threadIdx.x;
    int m0 = blockIdx.x * 128;
    int tx = tid & 15, ty = tid >> 4;

    unsigned long long acc2[8][4];
    #pragma unroll
    for (int i = 0; i < 8; i++)
        #pragma unroll
        for (int j = 0; j < 4; j++) acc2[i][j] = 0ULL;  // {+0.f, +0.f}

    for (int kk = 0; kk < 128; kk += 16) {
        #pragma unroll
        for (int p = 0; p < 2; p++) {
            int f = tid * 2 + p;
            int k = f >> 5, n4 = f & 31;
            ((float4*)Ws[k])[n4] = ((const float4*)W)[(kk + k) * 32 + n4];
        }
        #pragma unroll
        for (int p = 0; p < 2; p++) {
            int f = tid * 2 + p;
            int r = f >> 2, c4 = f & 3;
            int row = m0 + r;
            int col = kk + c4 * 4;
            float4 v = make_float4(0.f, 0.f, 0.f, 0.f);
            if (row < NN) v = *(const float4*)(A + row * CC + col);
            if (fuse) {
                float4 sc = *(const float4*)(g_scale + col);
                float4 sh = *(const float4*)(g_shift + col);
                v.x = fmaxf(fmaf(v.x, sc.x, sh.x), 0.f);
                v.y = fmaxf(fmaf(v.y, sc.y, sh.y), 0.f);
                v.z = fmaxf(fmaf(v.z, sc.z, sh.z), 0.f);
                v.w = fmaxf(fmaf(v.w, sc.w, sh.w), 0.f);
            }
            As[c4 * 4 + 0][r] = v.x;
            As[c4 * 4 + 1][r] = v.y;
            As[c4 * 4 + 2][r] = v.z;
            As[c4 * 4 + 3][r] = v.w;
        }
        __syncthreads();
        #pragma unroll
        for (int k = 0; k < 16; k++) {
            float a[8];
            unsigned long long bb[4];
            *(float4*)(a)     = *(float4*)&As[k][ty * 4];
            *(float4*)(a + 4) = *(float4*)&As[k][64 + ty * 4];
            {
                ulonglong2 t0 = *(ulonglong2*)&Ws[k][tx * 4];
                ulonglong2 t1 = *(ulonglong2*)&Ws[k][64 + tx * 4];
                bb[0] = t0.x; bb[1] = t0.y; bb[2] = t1.x; bb[3] = t1.y;
            }
            #pragma unroll
            for (int i = 0; i < 8; i++) {
                unsigned long long ai = bcast2(a[i]);
                fma2(acc2[i][0], ai, bb[0]);
                fma2(acc2[i][1], ai, bb[1]);
                fma2(acc2[i][2], ai, bb[2]);
                fma2(acc2[i][3], ai, bb[3]);
            }
        }
        __syncthreads();
    }
    #pragma unroll
    for (int i = 0; i < 8; i++) {
        int row = m0 + ((i < 4) ? (ty * 4 + i) : (64 + ty * 4 + (i - 4)));
        if (row < NN) {
            U64F2 p0, p1, p2, p3;
            p0.u = acc2[i][0]; p1.u = acc2[i][1];
            p2.u = acc2[i][2]; p3.u = acc2[i][3];
            __nv_bfloat162 b0 = __floats2bfloat162_rn(p0.f.x, p0.f.y);
            __nv_bfloat162 b1 = __floats2bfloat162_rn(p1.f.x, p1.f.y);
            __nv_bfloat162 b2 = __floats2bfloat162_rn(p2.f.x, p2.f.y);
            __nv_bfloat162 b3 = __floats2bfloat162_rn(p3.f.x, p3.f.y);
            unsigned int u0 = *(unsigned int*)&b0;
            unsigned int u1 = *(unsigned int*)&b1;
            unsigned int u2 = *(unsigned int*)&b2;
            unsigned int u3 = *(unsigned int*)&b3;
            *(uint2*)(g_hb + row * 64 + tx * 2)      = make_uint2(u0, u1);
            *(uint2*)(g_hb + row * 64 + 32 + tx * 2) = make_uint2(u2, u3);
        }
    }
}

// ---------------- gather-style aggregation (pure; no BN tail) ---------------
// 64 threads/node, 2 channels each; 8 nodes per 512-thr block; grid = AGB.
__global__ void __launch_bounds__(512) aggregate_kernel() {
    int node = blockIdx.x * 8 + (threadIdx.x >> 6);   // grid exact: AGB*8 == NN
    int c = threadIdx.x & 63;
    int s = g_off[node], e = g_off[node + 1];
    float ax0 = 0.f, ay0 = 0.f, ax1 = 0.f, ay1 = 0.f;
    int j = s;
    for (; j + 1 < e; j += 2) {
        int2 e0 = g_edge[j];
        int2 e1 = g_edge[j + 1];
        unsigned int u0 = g_hb[e0.x * 64 + c];
        unsigned int u1 = g_hb[e1.x * 64 + c];
        float2 f0 = __bfloat1622float2(*(__nv_bfloat162*)&u0);
        float2 f1 = __bfloat1622float2(*(__nv_bfloat162*)&u1);
        float w0 = __int_as_float(e0.y);
        float w1 = __int_as_float(e1.y);
        ax0 += w0 * f0.x; ay0 += w0 * f0.y;
        ax1 += w1 * f1.x; ay1 += w1 * f1.y;
    }
    if (j < e) {
        int2 e0 = g_edge[j];
        unsigned int u0 = g_hb[e0.x * 64 + c];
        float2 f0 = __bfloat1622float2(*(__nv_bfloat162*)&u0);
        float w0 = __int_as_float(e0.y);
        ax0 += w0 * f0.x; ay0 += w0 * f0.y;
    }
    *(float2*)(g_agg + node * CC + 2 * c) = make_float2(ax0 + ax1, ay0 + ay1);
}

// ---------------- BN stats with fused last-block finalize (R5-proven) -------
__global__ void __launch_bounds__(256) stats_kernel(const float* __restrict__ gam,
                                                    const float* __restrict__ bet) {
    __shared__ float ssum[256];
    __shared__ float ssq[256];
    __shared__ int slast;
    int c = threadIdx.x & 127;
    int sub = threadIdx.x >> 7;  // 0..1
    const int rpb = (NN + SBLK - 1) / SBLK;  // 250
    int r0 = blockIdx.x * rpb;
    int r1 = min(NN, r0 + rpb);
    float s = 0.f, s2 = 0.f;
    for (int r = r0 + sub; r < r1; r += 2) {
        float v = g_agg[r * CC + c];
        s += v; s2 += v * v;
    }
    ssum[threadIdx.x] = s;
    ssq[threadIdx.x] = s2;
    __syncthreads();
    if (threadIdx.x < 128) {
        g_psum[blockIdx.x * CC + c] = ssum[c] + ssum[c + 128];
        g_psq[blockIdx.x * CC + c]  = ssq[c] + ssq[c + 128];
    }
    __threadfence();
    if (threadIdx.x == 0)
        slast = (atomicAdd(&g_cnt, 1) == SBLK - 1) ? 1 : 0;
    __syncthreads();
    if (slast) {
        __threadfence();  // acquire: see all blocks' partials
        if (threadIdx.x < 128) {
            float ts = 0.f, ts2 = 0.f;
            for (int b = 0; b < SBLK; b++) {
                ts  += g_psum[b * CC + threadIdx.x];
                ts2 += g_psq[b * CC + threadIdx.x];
            }
            float mu = ts * (1.0f / NN);
            float var = fmaxf(ts2 * (1.0f / NN) - mu * mu, 0.f);
            float sc = gam[threadIdx.x] * rsqrtf(var + EPSV);
            g_scale[threadIdx.x] = sc;
            g_shift[threadIdx.x] = bet[threadIdx.x] - mu * sc;
        }
        __syncthreads();
        if (threadIdx.x == 0) g_cnt = 0;  // reset for next layer / replay
    }
}

// ---------------- pool + head (512 thr; bounds inlined; layer-3 BN fused) ---
__global__ void __launch_bounds__(512) pool_head_kernel(const void* batch_raw,
                                                        const float* __restrict__ Wh,
                                                        const float* __restrict__ bh,
                                                        float* __restrict__ out) {
    __shared__ float part[512];
    __shared__ float pooled[CC];
    __shared__ int sb[2];
    int g = blockIdx.x;
    int t = threadIdx.x;
    int c = t & 127;
    int sub = t >> 7;  // 0..3
    if (t < 2) {
        int target = g + t;
        int lo = 0, hi = NN;
        if (g_bis64) {
            const long long* b = (const long long*)batch_raw;
            while (lo < hi) { int mid = (lo + hi) >> 1; if (b[mid] < (long long)target) lo = mid + 1; else hi = mid; }
        } else {
            const int* b = (const int*)batch_raw;
            while (lo < hi) { int mid = (lo + hi) >> 1; if (b[mid] < target) lo = mid + 1; else hi = mid; }
        }
        sb[t] = lo;
    }
    __syncthreads();
    int s = sb[0], e = sb[1];
    float sc = g_scale[c], sh = g_shift[c];
    float a = 0.f;
    for (int r = s + sub; r < e; r += 4)
        a += fmaxf(fmaf(g_agg[r * CC + c], sc, sh), 0.f);
    part[t] = a;
    __syncthreads();
    if (t < 128) {
        float cnt = (float)(e - s);
        pooled[t] = (part[t] + part[t + 128] + part[t + 256] + part[t + 384])
                    / fmaxf(cnt, 1.0f);
    }
    __syncthreads();
    if (t < 8) {
        float o = bh[t];
        #pragma unroll 8
        for (int k = 0; k < CC; k++) o += pooled[k] * Wh[k * 8 + t];
        out[g * 8 + t] = o;
    }
}

// ---------------- launch ----------------
extern "C" void kernel_launch(void* const* d_in, const int* in_sizes, int n_in,
                              void* d_out, int out_size) {
    const float* x  = (const float*)d_in[0];
    const void*  ei = d_in[1];
    const void*  batch = d_in[2];
    const float* W[3]  = { (const float*)d_in[3],  (const float*)d_in[7],  (const float*)d_in[11] };
    const float* gg[3] = { (const float*)d_in[5],  (const float*)d_in[9],  (const float*)d_in[13] };
    const float* be[3] = { (const float*)d_in[6],  (const float*)d_in[10], (const float*)d_in[14] };
    const float* Wh = (const float*)d_in[15];
    const float* bh = (const float*)d_in[16];
    float* out = (float*)d_out;

    const int EB = (NE + 255) / 256;   // 2344

    zero_prep_kernel<<<NB, 256>>>((const int*)ei, (const int*)batch);
    prep_kernel<<<EB, 256>>>(ei);
    scan1_kernel<<<NB, 256>>>();
    scan23_kernel<<<NB, 256>>>();
    fill_kernel<<<EB, 256>>>(ei);

    for (int l = 0; l < 3; l++) {
        gemm_kernel<<<(NN + 127) / 128, 256>>>(x, W[l], l == 0 ? 0 : 1);
        aggregate_kernel<<<AGB, 512>>>();
        stats_kernel<<<SBLK, 256>>>(gg[l], be[l]);
    }

    pool_head_kernel<<<NG, 512>>>(batch, Wh, bh, out);
}